// round 2
// baseline (speedup 1.0000x reference)
#include <cuda_runtime.h>
#include <math.h>

#define BATCH 4
#define CDIM  2048
#define EDIM  1024

// Scratch (allocation-free rule: __device__ globals)
__device__ float g_y   [(size_t)BATCH * CDIM * EDIM];   // 32 MiB
__device__ float g_z   [(size_t)BATCH * CDIM * EDIM];   // 32 MiB (yx^T: [b,k,e])
__device__ float g_vx  [(size_t)BATCH * CDIM * EDIM];   // 32 MiB
__device__ float g_attn[(size_t)BATCH * CDIM * CDIM];   // 64 MiB
__device__ int   g_mask_mode;                           // 0=u8, 1=i32, 2=f32

// ---------------------------------------------------------------------------
// Detect how the harness encoded the boolean mask. Word values:
//   float32 : {0x00000000, 0x3F800000}
//   int32   : {0, 1}
//   uint8x4 : bytes each 0/1 -> words like 0x01000100 (>1, never 0x3F800000)
// ---------------------------------------------------------------------------
__global__ void detect_mask_kernel(const unsigned int* __restrict__ w, int nwords)
{
    __shared__ int sawFloat, sawMulti;
    if (threadIdx.x == 0) { sawFloat = 0; sawMulti = 0; }
    __syncthreads();
    for (int i = threadIdx.x; i < nwords; i += blockDim.x) {
        unsigned int v = w[i];
        if (v == 0x3F800000u)      atomicOr(&sawFloat, 1);
        else if (v > 1u)           atomicOr(&sawMulti, 1);
    }
    __syncthreads();
    if (threadIdx.x == 0)
        g_mask_mode = sawFloat ? 2 : (sawMulti ? 0 : 1);
}

// ---------------------------------------------------------------------------
// Tiled SGEMM: C[m,n] = sum_k A[m,k] * B'[k,n]  (+bias)
//   TRANSB=false: B is [K,N] row-major (NN)
//   TRANSB=true : B is [N,K] row-major (NT), C[m,n] = sum_k A[m,k]*B[n,k]
//   BIAS: 0=none, 1=per-col (bias[n]), 2=per-row (bias[m])
// Block tile 128x128, K-tile 16, 256 threads, 8x8 per-thread microtile.
// ---------------------------------------------------------------------------
template<bool TRANSB, int BIAS>
__launch_bounds__(256, 2)
__global__ void gemm128(const float* __restrict__ Ag, const float* __restrict__ Bg,
                        const float* __restrict__ bias, float* __restrict__ Cg,
                        int M, int N, int K, int lda, int ldb, int ldc,
                        long long sA, long long sB, long long sC)
{
    const float* A = Ag + (long long)blockIdx.z * sA;
    const float* B = Bg + (long long)blockIdx.z * sB;
    float*       C = Cg + (long long)blockIdx.z * sC;

    __shared__ float As[16][128];   // k-major (transposed on store)
    __shared__ float Bs[16][128];   // k-major

    const int tid = threadIdx.x;
    const int tx = tid & 15;        // 0..15 -> 8 output cols each
    const int ty = tid >> 4;        // 0..15 -> 8 output rows each
    const int row0 = blockIdx.y * 128;
    const int col0 = blockIdx.x * 128;

    float acc[8][8];
    #pragma unroll
    for (int i = 0; i < 8; i++)
        #pragma unroll
        for (int j = 0; j < 8; j++) acc[i][j] = 0.f;

    for (int kt0 = 0; kt0 < K; kt0 += 16) {
        // --- load A tile: 128 rows x 16 k (row-major, k contiguous) ---
        #pragma unroll
        for (int l = 0; l < 2; l++) {
            int f  = tid + l * 256;           // float4 id in [0,512)
            int r  = f >> 2;                  // row within tile
            int kv = (f & 3) << 2;            // k sub-offset
            float4 v = *reinterpret_cast<const float4*>(
                A + (long long)(row0 + r) * lda + kt0 + kv);
            As[kv + 0][r] = v.x; As[kv + 1][r] = v.y;
            As[kv + 2][r] = v.z; As[kv + 3][r] = v.w;
        }
        // --- load B tile ---
        if (TRANSB) {
            #pragma unroll
            for (int l = 0; l < 2; l++) {
                int f  = tid + l * 256;
                int r  = f >> 2;              // n within tile
                int kv = (f & 3) << 2;
                float4 v = *reinterpret_cast<const float4*>(
                    B + (long long)(col0 + r) * ldb + kt0 + kv);
                Bs[kv + 0][r] = v.x; Bs[kv + 1][r] = v.y;
                Bs[kv + 2][r] = v.z; Bs[kv + 3][r] = v.w;
            }
        } else {
            #pragma unroll
            for (int l = 0; l < 2; l++) {
                int f  = tid + l * 256;
                int r  = f >> 5;              // k within tile (0..15)
                int nv = (f & 31) << 2;       // n sub-offset
                float4 v = *reinterpret_cast<const float4*>(
                    B + (long long)(kt0 + r) * ldb + col0 + nv);
                *reinterpret_cast<float4*>(&Bs[r][nv]) = v;
            }
        }
        __syncthreads();

        #pragma unroll
        for (int kk = 0; kk < 16; kk++) {
            float a[8], b[8];
            *reinterpret_cast<float4*>(a)     = *reinterpret_cast<const float4*>(&As[kk][ty * 8]);
            *reinterpret_cast<float4*>(a + 4) = *reinterpret_cast<const float4*>(&As[kk][ty * 8 + 4]);
            *reinterpret_cast<float4*>(b)     = *reinterpret_cast<const float4*>(&Bs[kk][tx * 8]);
            *reinterpret_cast<float4*>(b + 4) = *reinterpret_cast<const float4*>(&Bs[kk][tx * 8 + 4]);
            #pragma unroll
            for (int i = 0; i < 8; i++)
                #pragma unroll
                for (int j = 0; j < 8; j++)
                    acc[i][j] = fmaf(a[i], b[j], acc[i][j]);
        }
        __syncthreads();
    }

    // --- epilogue ---
    #pragma unroll
    for (int i = 0; i < 8; i++) {
        int r = row0 + ty * 8 + i;
        float rb = (BIAS == 2) ? bias[r] : 0.f;
        #pragma unroll
        for (int j = 0; j < 8; j += 4) {
            int c = col0 + tx * 8 + j;
            float4 v;
            v.x = acc[i][j];     v.y = acc[i][j + 1];
            v.z = acc[i][j + 2]; v.w = acc[i][j + 3];
            if (BIAS == 1) {
                v.x += bias[c];     v.y += bias[c + 1];
                v.z += bias[c + 2]; v.w += bias[c + 3];
            } else if (BIAS == 2) {
                v.x += rb; v.y += rb; v.z += rb; v.w += rb;
            }
            *reinterpret_cast<float4*>(C + (long long)r * ldc + c) = v;
        }
    }
}

// ---------------------------------------------------------------------------
// Masked softmax over last dim (k = CDIM). One block (256 thr) per (b,c) row.
// attn = softmax(where(mask, -inf, attn) * rsqrt(C))
// Mask decoded per g_mask_mode (0=u8, 1=i32, 2=f32).
// ---------------------------------------------------------------------------
__global__ void softmax_kernel(float* __restrict__ attn,
                               const void* __restrict__ mask_raw)
{
    const long long row = blockIdx.x;                 // b*C + c
    float* p = attn + row * CDIM;
    const float scale = rsqrtf((float)CDIM);
    const int tid = threadIdx.x;
    const int mode = g_mask_mode;

    const unsigned char* mb = (const unsigned char*)mask_raw + row * CDIM;
    const int*           mi = (const int*)mask_raw          + row * CDIM;
    const float*         mf = (const float*)mask_raw        + row * CDIM;

    float v[8];
    bool mm[8];
    float lmax = -INFINITY;
    #pragma unroll
    for (int i = 0; i < 8; i++) {
        int e = tid + i * 256;
        bool masked;
        if      (mode == 0) masked = (mb[e] != 0);
        else if (mode == 1) masked = (mi[e] != 0);
        else                masked = (mf[e] != 0.f);
        mm[i] = masked;
        float t = masked ? -INFINITY : p[e] * scale;
        v[i] = t;
        lmax = fmaxf(lmax, t);
    }

    __shared__ float red[256];
    red[tid] = lmax; __syncthreads();
    #pragma unroll
    for (int s = 128; s > 0; s >>= 1) {
        if (tid < s) red[tid] = fmaxf(red[tid], red[tid + s]);
        __syncthreads();
    }
    const float rmax = red[0];
    __syncthreads();

    float lsum = 0.f;
    #pragma unroll
    for (int i = 0; i < 8; i++) {
        v[i] = mm[i] ? 0.f : __expf(v[i] - rmax);
        lsum += v[i];
    }
    red[tid] = lsum; __syncthreads();
    #pragma unroll
    for (int s = 128; s > 0; s >>= 1) {
        if (tid < s) red[tid] += red[tid + s];
        __syncthreads();
    }
    const float inv = 1.f / red[0];
    #pragma unroll
    for (int i = 0; i < 8; i++)
        p[tid + i * 256] = v[i] * inv;
}

// ---------------------------------------------------------------------------
extern "C" void kernel_launch(void* const* d_in, const int* in_sizes, int n_in,
                              void* d_out, int out_size)
{
    const float* x     = (const float*)d_in[0];   // [B,C,E]
    const float* fc_w  = (const float*)d_in[1];   // [E,E]
    const float* fc_b  = (const float*)d_in[2];   // [E]
    const float* alt_w = (const float*)d_in[3];   // [C,C]
    const float* alt_b = (const float*)d_in[4];   // [C]
    const float* v_w   = (const float*)d_in[5];   // [E,E]
    const float* v_b   = (const float*)d_in[6];   // [E]
    const void*  mask  = d_in[7];                 // [B,C,C] bool (encoding detected)
    float* out = (float*)d_out;                   // [B,C,E]

    float *y, *z, *vx, *attn;
    cudaGetSymbolAddress((void**)&y,    g_y);
    cudaGetSymbolAddress((void**)&z,    g_z);
    cudaGetSymbolAddress((void**)&vx,   g_vx);
    cudaGetSymbolAddress((void**)&attn, g_attn);

    const long long sCE = (long long)CDIM * EDIM;   // per-batch stride [C,E]
    const long long sCC = (long long)CDIM * CDIM;   // per-batch stride [C,C]
    dim3 blk(256);

    // 0) detect mask encoding (16K words is plenty; smallest case has 4M words)
    detect_mask_kernel<<<1, 256>>>((const unsigned int*)mask, 16384);

    // 1) y[b,c,f] = sum_e x[b,c,e]*fc_w[f,e] + fc_b[f]        (NT, col bias)
    gemm128<true, 1><<<dim3(EDIM / 128, CDIM / 128, BATCH), blk>>>(
        x, fc_w, fc_b, y, CDIM, EDIM, EDIM, EDIM, EDIM, EDIM, sCE, 0, sCE);

    // 2) vx[b,k,f] = sum_e x[b,k,e]*v_w[f,e] + v_b[f]         (NT, col bias)
    gemm128<true, 1><<<dim3(EDIM / 128, CDIM / 128, BATCH), blk>>>(
        x, v_w, v_b, vx, CDIM, EDIM, EDIM, EDIM, EDIM, EDIM, sCE, 0, sCE);

    // 3) z[b,k,e] = sum_c alt_w[k,c]*x[b,c,e] + alt_b[k]      (NN, row bias)
    //    (z = yx^T so the attn GEMM below is a clean NT)
    gemm128<false, 2><<<dim3(EDIM / 128, CDIM / 128, BATCH), blk>>>(
        alt_w, x, alt_b, z, CDIM, EDIM, CDIM, CDIM, EDIM, EDIM, 0, sCE, sCE);

    // 4) attn[b,c,k] = sum_e y[b,c,e]*z[b,k,e]                (NT, no bias)
    gemm128<true, 0><<<dim3(CDIM / 128, CDIM / 128, BATCH), blk>>>(
        y, z, nullptr, attn, CDIM, CDIM, EDIM, EDIM, EDIM, CDIM, sCE, sCE, sCC);

    // 5) masked softmax over k (mask decoded per detected mode)
    softmax_kernel<<<BATCH * CDIM, 256>>>(attn, mask);

    // 6) out[b,c,e] = sum_k attn[b,c,k]*vx[b,k,e]             (NN, no bias)
    gemm128<false, 0><<<dim3(EDIM / 128, CDIM / 128, BATCH), blk>>>(
        attn, vx, nullptr, out, CDIM, EDIM, CDIM, CDIM, EDIM, EDIM, sCC, sCE, sCE);
}

// round 4
// speedup vs baseline: 3.1595x; 3.1595x over previous
#include <cuda_runtime.h>
#include <cstdint>
#include <math.h>

#define BATCH 4
#define CDIM  2048
#define EDIM  1024

// ------------------------- scratch (__device__ globals) ---------------------
__device__ float g_y    [(size_t)BATCH * CDIM * EDIM];  // y    [b,C,E] (tf32-rounded)
__device__ float g_z    [(size_t)BATCH * CDIM * EDIM];  // z    [b,C,E] (rounded)
__device__ float g_vxT  [(size_t)BATCH * CDIM * EDIM];  // vxT  [b,E,C] (rounded)
__device__ float g_xT   [(size_t)BATCH * CDIM * EDIM];  // xT   [b,E,C] (rounded)
__device__ float g_xr   [(size_t)BATCH * CDIM * EDIM];  // x    rounded
__device__ float g_attn [(size_t)BATCH * CDIM * CDIM];  // attn [b,C,C]
__device__ float g_fcw  [(size_t)EDIM * EDIM];          // rounded weights
__device__ float g_vw   [(size_t)EDIM * EDIM];
__device__ float g_altw [(size_t)CDIM * CDIM];
__device__ int   g_mask_mode;                           // 0=u8, 1=i32, 2=f32

// ------------------------- helpers ------------------------------------------
__device__ __forceinline__ float rtf32(float x) {
    float r;
    asm("cvt.rna.tf32.f32 %0, %1;" : "=f"(r) : "f"(x));
    return r;
}
__device__ __forceinline__ uint32_t smem_u32(const void* p) {
    uint32_t a;
    asm("{ .reg .u64 t; cvta.to.shared.u64 t, %1; cvt.u32.u64 %0, t; }"
        : "=r"(a) : "l"(p));
    return a;
}
__device__ __forceinline__ void mma_tf32(float* c, const unsigned* a, const unsigned* b) {
    asm volatile(
        "mma.sync.aligned.m16n8k8.row.col.f32.tf32.tf32.f32 "
        "{%0,%1,%2,%3}, {%4,%5,%6,%7}, {%8,%9}, {%0,%1,%2,%3};"
        : "+f"(c[0]), "+f"(c[1]), "+f"(c[2]), "+f"(c[3])
        : "r"(a[0]), "r"(a[1]), "r"(a[2]), "r"(a[3]), "r"(b[0]), "r"(b[1]));
}
#define CP_COMMIT() asm volatile("cp.async.commit_group;" ::: "memory")
#define CP_WAIT(n)  asm volatile("cp.async.wait_group %0;" :: "n"(n) : "memory")

// ------------------------- mask-mode detection ------------------------------
__global__ void detect_mask_kernel(const unsigned int* __restrict__ w, int nwords)
{
    __shared__ int sawFloat, sawMulti;
    if (threadIdx.x == 0) { sawFloat = 0; sawMulti = 0; }
    __syncthreads();
    for (int i = threadIdx.x; i < nwords; i += blockDim.x) {
        unsigned int v = w[i];
        if (v == 0x3F800000u) atomicOr(&sawFloat, 1);
        else if (v > 1u)      atomicOr(&sawMulti, 1);
    }
    __syncthreads();
    if (threadIdx.x == 0)
        g_mask_mode = sawFloat ? 2 : (sawMulti ? 0 : 1);
}

// ------------------------- tf32 rounding (elementwise) ----------------------
__global__ void round_kernel(const float4* __restrict__ in, float4* __restrict__ out, int n4)
{
    int i = blockIdx.x * 256 + threadIdx.x;
    if (i < n4) {
        float4 v = in[i];
        v.x = rtf32(v.x); v.y = rtf32(v.y);
        v.z = rtf32(v.z); v.w = rtf32(v.w);
        out[i] = v;
    }
}

// ------------------------- transpose [C,E] -> [E,C], tf32-rounded -----------
__global__ void transpose_kernel(const float* __restrict__ in, float* __restrict__ out)
{
    __shared__ float t[32][33];
    const long long boff = (long long)blockIdx.z * CDIM * EDIM;
    const int e0 = blockIdx.x * 32, c0 = blockIdx.y * 32;
    const int tx = threadIdx.x, ty = threadIdx.y;   // (32, 8)
    #pragma unroll
    for (int j = 0; j < 32; j += 8)
        t[ty + j][tx] = in[boff + (long long)(c0 + ty + j) * EDIM + e0 + tx];
    __syncthreads();
    #pragma unroll
    for (int j = 0; j < 32; j += 8)
        out[boff + (long long)(e0 + ty + j) * CDIM + c0 + tx] = rtf32(t[tx][ty + j]);
}

// ---------------------------------------------------------------------------
// TF32 mma.sync NT GEMM: C[m,n] = sum_k A[m,k]*B[n,k]  (+bias, opt. tf32 round)
// Block 128x128, K-chunk 32, 4 warps (2x2, warp tile 64x64), cp.async 2-stage.
// Smem rows padded to 36 floats -> fragment LDS is bank-conflict-free.
// BIAS: 0=none, 1=per-col bias[n], 2=per-row bias[m].
// ---------------------------------------------------------------------------
#define LDP 36
#define STAGE_FLOATS (128 * LDP)
#define SMEM_DYN (4 * STAGE_FLOATS * 4)     // A0,B0,A1,B1 = 73728 B

__device__ __forceinline__ void cp_tile(float* sm, const float* gsrc, int ld, int tid)
{
    #pragma unroll
    for (int l = 0; l < 8; l++) {
        int idx = tid + l * 128;
        int r = idx >> 3, cb = (idx & 7) << 2;       // row, float-offset
        uint32_t dst = smem_u32(sm + r * LDP + cb);
        const float* src = gsrc + (long long)r * ld + cb;
        asm volatile("cp.async.cg.shared.global [%0], [%1], 16;"
                     :: "r"(dst), "l"(src) : "memory");
    }
}

template<int BIAS, int ROUND>
__global__ void __launch_bounds__(128, 2)
gemm_mma(const float* __restrict__ Ag, const float* __restrict__ Bg,
         const float* __restrict__ bias, float* __restrict__ Cg,
         int K, int lda, int ldb, int ldc,
         long long sA, long long sB, long long sC)
{
    extern __shared__ float sm[];
    float* Ast[2] = { sm,                    sm + 2 * STAGE_FLOATS };
    float* Bst[2] = { sm + STAGE_FLOATS,     sm + 3 * STAGE_FLOATS };

    const int tid  = threadIdx.x;
    const int lane = tid & 31;
    const int wid  = tid >> 5;
    const int wm   = (wid & 1) * 64;
    const int wn   = (wid >> 1) * 64;
    const int g    = lane >> 2;
    const int tc   = lane & 3;

    const float* A = Ag + (long long)blockIdx.z * sA + (long long)(blockIdx.y * 128) * lda;
    const float* B = Bg + (long long)blockIdx.z * sB + (long long)(blockIdx.x * 128) * ldb;

    float acc[4][8][4];
    #pragma unroll
    for (int i = 0; i < 4; i++)
        #pragma unroll
        for (int j = 0; j < 8; j++)
            #pragma unroll
            for (int k = 0; k < 4; k++) acc[i][j][k] = 0.f;

    const int nk = K >> 5;
    cp_tile(Ast[0], A, lda, tid);
    cp_tile(Bst[0], B, ldb, tid);
    CP_COMMIT();

    for (int i = 0; i < nk; i++) {
        const int s = i & 1;
        if (i + 1 < nk) {
            cp_tile(Ast[s ^ 1], A + (i + 1) * 32, lda, tid);
            cp_tile(Bst[s ^ 1], B + (i + 1) * 32, ldb, tid);
            CP_COMMIT();
            CP_WAIT(1);
        } else {
            CP_WAIT(0);
        }
        __syncthreads();

        const float* As = Ast[s];
        const float* Bs = Bst[s];
        #pragma unroll
        for (int ks = 0; ks < 4; ks++) {
            const int c0 = ks * 8;
            unsigned a[4][4], b[8][2];
            #pragma unroll
            for (int mf = 0; mf < 4; mf++) {
                const float* p = As + (wm + mf * 16 + g) * LDP + c0 + tc;
                a[mf][0] = __float_as_uint(p[0]);
                a[mf][1] = __float_as_uint(p[8 * LDP]);
                a[mf][2] = __float_as_uint(p[4]);
                a[mf][3] = __float_as_uint(p[8 * LDP + 4]);
            }
            #pragma unroll
            for (int nf = 0; nf < 8; nf++) {
                const float* p = Bs + (wn + nf * 8 + g) * LDP + c0 + tc;
                b[nf][0] = __float_as_uint(p[0]);
                b[nf][1] = __float_as_uint(p[4]);
            }
            #pragma unroll
            for (int mf = 0; mf < 4; mf++)
                #pragma unroll
                for (int nf = 0; nf < 8; nf++)
                    mma_tf32(acc[mf][nf], a[mf], b[nf]);
        }
        __syncthreads();
    }

    // ------------------------- epilogue -------------------------------------
    float* Cb = Cg + (long long)blockIdx.z * sC;
    #pragma unroll
    for (int mf = 0; mf < 4; mf++) {
        #pragma unroll
        for (int nf = 0; nf < 8; nf++) {
            const int r0 = blockIdx.y * 128 + wm + mf * 16 + g;
            const int c  = blockIdx.x * 128 + wn + nf * 8 + 2 * tc;
            float v0 = acc[mf][nf][0], v1 = acc[mf][nf][1];
            float v2 = acc[mf][nf][2], v3 = acc[mf][nf][3];
            if (BIAS == 1) {
                const float b0 = bias[c], b1 = bias[c + 1];
                v0 += b0; v1 += b1; v2 += b0; v3 += b1;
            } else if (BIAS == 2) {
                const float br0 = bias[r0], br1 = bias[r0 + 8];
                v0 += br0; v1 += br0; v2 += br1; v3 += br1;
            }
            if (ROUND) {
                v0 = rtf32(v0); v1 = rtf32(v1);
                v2 = rtf32(v2); v3 = rtf32(v3);
            }
            float2 p0 = make_float2(v0, v1);
            float2 p1 = make_float2(v2, v3);
            *reinterpret_cast<float2*>(Cb + (long long)r0 * ldc + c)       = p0;
            *reinterpret_cast<float2*>(Cb + (long long)(r0 + 8) * ldc + c) = p1;
        }
    }
}

// ------------------------- masked softmax over k (tf32-rounded out) ---------
__global__ void softmax_kernel(float* __restrict__ attn,
                               const void* __restrict__ mask_raw)
{
    const long long row = blockIdx.x;
    float* p = attn + row * CDIM;
    const float scale = rsqrtf((float)CDIM);
    const int tid = threadIdx.x;
    const int mode = g_mask_mode;

    const unsigned char* mb = (const unsigned char*)mask_raw + row * CDIM;
    const int*           mi = (const int*)mask_raw          + row * CDIM;
    const float*         mf = (const float*)mask_raw        + row * CDIM;

    float v[8];
    bool mm[8];
    float lmax = -INFINITY;
    #pragma unroll
    for (int i = 0; i < 8; i++) {
        int e = tid + i * 256;
        bool masked;
        if      (mode == 0) masked = (mb[e] != 0);
        else if (mode == 1) masked = (mi[e] != 0);
        else                masked = (mf[e] != 0.f);
        mm[i] = masked;
        float t = masked ? -INFINITY : p[e] * scale;
        v[i] = t;
        lmax = fmaxf(lmax, t);
    }

    __shared__ float red[256];
    red[tid] = lmax; __syncthreads();
    #pragma unroll
    for (int s = 128; s > 0; s >>= 1) {
        if (tid < s) red[tid] = fmaxf(red[tid], red[tid + s]);
        __syncthreads();
    }
    const float rmax = red[0];
    __syncthreads();

    float lsum = 0.f;
    #pragma unroll
    for (int i = 0; i < 8; i++) {
        v[i] = mm[i] ? 0.f : __expf(v[i] - rmax);
        lsum += v[i];
    }
    red[tid] = lsum; __syncthreads();
    #pragma unroll
    for (int s = 128; s > 0; s >>= 1) {
        if (tid < s) red[tid] += red[tid + s];
        __syncthreads();
    }
    const float inv = 1.f / red[0];
    #pragma unroll
    for (int i = 0; i < 8; i++)
        p[tid + i * 256] = rtf32(v[i] * inv);
}

// ---------------------------------------------------------------------------
extern "C" void kernel_launch(void* const* d_in, const int* in_sizes, int n_in,
                              void* d_out, int out_size)
{
    const float* x     = (const float*)d_in[0];   // [B,C,E]
    const float* fc_w  = (const float*)d_in[1];   // [E,E]
    const float* fc_b  = (const float*)d_in[2];   // [E]
    const float* alt_w = (const float*)d_in[3];   // [C,C]
    const float* alt_b = (const float*)d_in[4];   // [C]
    const float* v_w   = (const float*)d_in[5];   // [E,E]
    const float* v_b   = (const float*)d_in[6];   // [E]
    const void*  mask  = d_in[7];                 // [B,C,C] bool (encoding detected)
    float* out = (float*)d_out;                   // [B,C,E]

    float *y, *z, *vxT, *xT, *xr, *attn, *fcw, *vw, *altw;
    cudaGetSymbolAddress((void**)&y,    g_y);
    cudaGetSymbolAddress((void**)&z,    g_z);
    cudaGetSymbolAddress((void**)&vxT,  g_vxT);
    cudaGetSymbolAddress((void**)&xT,   g_xT);
    cudaGetSymbolAddress((void**)&xr,   g_xr);
    cudaGetSymbolAddress((void**)&attn, g_attn);
    cudaGetSymbolAddress((void**)&fcw,  g_fcw);
    cudaGetSymbolAddress((void**)&vw,   g_vw);
    cudaGetSymbolAddress((void**)&altw, g_altw);

    cudaFuncSetAttribute(gemm_mma<0,0>, cudaFuncAttributeMaxDynamicSharedMemorySize, SMEM_DYN);
    cudaFuncSetAttribute(gemm_mma<1,1>, cudaFuncAttributeMaxDynamicSharedMemorySize, SMEM_DYN);
    cudaFuncSetAttribute(gemm_mma<2,1>, cudaFuncAttributeMaxDynamicSharedMemorySize, SMEM_DYN);

    const long long sCE = (long long)CDIM * EDIM;
    const long long sCC = (long long)CDIM * CDIM;
    dim3 blk(128);

    // 0) mask encoding + tf32 pre-rounding of all GEMM inputs
    detect_mask_kernel<<<1, 256>>>((const unsigned int*)mask, 16384);
    {
        int n4;
        n4 = (BATCH * CDIM * EDIM) / 4;
        round_kernel<<<(n4 + 255) / 256, 256>>>((const float4*)x, (float4*)xr, n4);
        n4 = (EDIM * EDIM) / 4;
        round_kernel<<<(n4 + 255) / 256, 256>>>((const float4*)fc_w, (float4*)fcw, n4);
        round_kernel<<<(n4 + 255) / 256, 256>>>((const float4*)v_w,  (float4*)vw,  n4);
        n4 = (CDIM * CDIM) / 4;
        round_kernel<<<(n4 + 255) / 256, 256>>>((const float4*)alt_w, (float4*)altw, n4);
    }
    // xT[b] = round(x[b]^T)  ([E,C])
    transpose_kernel<<<dim3(EDIM / 32, CDIM / 32, BATCH), dim3(32, 8)>>>(x, xT);

    // 1) y[c,f]   = sum_e x[c,e]*fc_w[f,e] + fc_b[f]      M=C,N=E,K=E (col bias, round)
    gemm_mma<1,1><<<dim3(EDIM / 128, CDIM / 128, BATCH), blk, SMEM_DYN>>>(
        xr, fcw, fc_b, y, EDIM, EDIM, EDIM, EDIM, sCE, 0, sCE);

    // 2) vxT[f,k] = sum_e v_w[f,e]*x[k,e] + v_b[f]        M=E,N=C,K=E (row bias, round)
    gemm_mma<2,1><<<dim3(CDIM / 128, EDIM / 128, BATCH), blk, SMEM_DYN>>>(
        vw, xr, v_b, vxT, EDIM, EDIM, EDIM, CDIM, 0, sCE, sCE);

    // 3) z[k,e]   = sum_c alt_w[k,c]*xT[e,c] + alt_b[k]   M=C,N=E,K=C (row bias, round)
    gemm_mma<2,1><<<dim3(EDIM / 128, CDIM / 128, BATCH), blk, SMEM_DYN>>>(
        altw, xT, alt_b, z, CDIM, CDIM, CDIM, EDIM, 0, sCE, sCE);

    // 4) attn[c,k] = sum_e y[c,e]*z[k,e]                  M=C,N=C,K=E (no bias)
    gemm_mma<0,0><<<dim3(CDIM / 128, CDIM / 128, BATCH), blk, SMEM_DYN>>>(
        y, z, nullptr, attn, EDIM, EDIM, EDIM, CDIM, sCE, sCE, sCC);

    // 5) masked softmax over k (tf32-rounded output)
    softmax_kernel<<<BATCH * CDIM, 256>>>(attn, mask);

    // 6) out[c,e] = sum_k attn[c,k]*vxT[e,k]              M=C,N=E,K=C (no bias)
    gemm_mma<0,0><<<dim3(EDIM / 128, CDIM / 128, BATCH), blk, SMEM_DYN>>>(
        attn, vxT, nullptr, out, CDIM, CDIM, CDIM, EDIM, sCC, sCE, sCE);
}

// round 5
// speedup vs baseline: 7.5893x; 2.4020x over previous
#include <cuda_runtime.h>
#include <cuda_fp16.h>
#include <cstdint>
#include <math.h>

#define BATCH 4
#define CDIM  2048
#define EDIM  1024

// ------------------------- scratch (__device__ globals) ---------------------
__device__ __half g_xh  [(size_t)BATCH * CDIM * EDIM];  // x    [b,C,E] fp16
__device__ __half g_xTh [(size_t)BATCH * CDIM * EDIM];  // xT   [b,E,C] fp16
__device__ __half g_yh  [(size_t)BATCH * CDIM * EDIM];  // y    [b,C,E] fp16
__device__ __half g_zh  [(size_t)BATCH * CDIM * EDIM];  // z    [b,C,E] fp16
__device__ __half g_vxTh[(size_t)BATCH * CDIM * EDIM];  // vxT  [b,E,C] fp16
__device__ __half g_fwh [(size_t)EDIM * EDIM];          // fp16 weights
__device__ __half g_vwh [(size_t)EDIM * EDIM];
__device__ __half g_awh [(size_t)CDIM * CDIM];
__device__ float  g_attn [(size_t)BATCH * CDIM * CDIM]; // attn logits f32
__device__ __half g_attnh[(size_t)BATCH * CDIM * CDIM]; // attn weights fp16
__device__ int    g_mask_mode;                          // 0=u8, 1=i32, 2=f32

// ------------------------- helpers ------------------------------------------
__device__ __forceinline__ uint32_t smem_u32(const void* p) {
    uint32_t a;
    asm("{ .reg .u64 t; cvta.to.shared.u64 t, %1; cvt.u32.u64 %0, t; }"
        : "=r"(a) : "l"(p));
    return a;
}
__device__ __forceinline__ void ldm_x4(unsigned* r, uint32_t addr) {
    asm volatile("ldmatrix.sync.aligned.m8n8.x4.shared.b16 {%0,%1,%2,%3}, [%4];"
                 : "=r"(r[0]), "=r"(r[1]), "=r"(r[2]), "=r"(r[3]) : "r"(addr));
}
__device__ __forceinline__ void mma_f16(float* c, const unsigned* a, const unsigned* b) {
    asm volatile(
        "mma.sync.aligned.m16n8k16.row.col.f32.f16.f16.f32 "
        "{%0,%1,%2,%3}, {%4,%5,%6,%7}, {%8,%9}, {%0,%1,%2,%3};"
        : "+f"(c[0]), "+f"(c[1]), "+f"(c[2]), "+f"(c[3])
        : "r"(a[0]), "r"(a[1]), "r"(a[2]), "r"(a[3]), "r"(b[0]), "r"(b[1]));
}
#define CP_COMMIT() asm volatile("cp.async.commit_group;" ::: "memory")
#define CP_WAIT(n)  asm volatile("cp.async.wait_group %0;" :: "n"(n) : "memory")

// ------------------------- mask-mode detection ------------------------------
__global__ void detect_mask_kernel(const unsigned int* __restrict__ w, int nwords)
{
    __shared__ int sawFloat, sawMulti;
    if (threadIdx.x == 0) { sawFloat = 0; sawMulti = 0; }
    __syncthreads();
    for (int i = threadIdx.x; i < nwords; i += blockDim.x) {
        unsigned int v = w[i];
        if (v == 0x3F800000u) atomicOr(&sawFloat, 1);
        else if (v > 1u)      atomicOr(&sawMulti, 1);
    }
    __syncthreads();
    if (threadIdx.x == 0)
        g_mask_mode = sawFloat ? 2 : (sawMulti ? 0 : 1);
}

// ------------------------- f32 -> f16 conversion ----------------------------
__global__ void cvt_kernel(const float4* __restrict__ in, __half2* __restrict__ out, int n4)
{
    int i = blockIdx.x * 256 + threadIdx.x;
    if (i < n4) {
        float4 v = in[i];
        out[2 * i]     = __floats2half2_rn(v.x, v.y);
        out[2 * i + 1] = __floats2half2_rn(v.z, v.w);
    }
}

// ------------------------- transpose [C,E] -> [E,C] + cvt -------------------
__global__ void transpose_kernel(const float* __restrict__ in, __half* __restrict__ out)
{
    __shared__ float t[32][33];
    const long long boff = (long long)blockIdx.z * CDIM * EDIM;
    const int e0 = blockIdx.x * 32, c0 = blockIdx.y * 32;
    const int tx = threadIdx.x, ty = threadIdx.y;   // (32, 8)
    #pragma unroll
    for (int j = 0; j < 32; j += 8)
        t[ty + j][tx] = in[boff + (long long)(c0 + ty + j) * EDIM + e0 + tx];
    __syncthreads();
    #pragma unroll
    for (int j = 0; j < 32; j += 8)
        out[boff + (long long)(e0 + ty + j) * CDIM + c0 + tx] = __float2half_rn(t[tx][ty + j]);
}

// ---------------------------------------------------------------------------
// FP16 mma.sync NT GEMM: C[m,n] = sum_k A[m,k]*B[n,k]  (+f32 bias)
// Block 128x128, K-chunk 64 halves (128B rows, SW128 XOR swizzle),
// 4 warps (2x2, warp tile 64x64), cp.async 2-stage, ldmatrix.x4 fragments.
// BIAS: 0=none, 1=per-col bias[n], 2=per-row bias[m]. OUTF: 1=f32 out, 0=f16.
// ---------------------------------------------------------------------------
#define STAGE_BYTES 32768                 // A 16KB + B 16KB
#define SMEM_DYN   (2 * STAGE_BYTES)

__device__ __forceinline__ void cp_tile_h(uint32_t base, const __half* g, int ld, int tid)
{
    #pragma unroll
    for (int l = 0; l < 8; l++) {
        int idx = tid + l * 128;          // 0..1023
        int r  = idx >> 3;                // 0..127
        int cb = (idx & 7) << 4;          // byte col 0..112
        uint32_t dst = base + r * 128 + (cb ^ ((r & 7) << 4));
        const __half* src = g + (long long)r * ld + (cb >> 1);
        asm volatile("cp.async.cg.shared.global [%0], [%1], 16;"
                     :: "r"(dst), "l"(src) : "memory");
    }
}

template<int BIAS, int OUTF>
__global__ void __launch_bounds__(128, 2)
gemm_h(const __half* __restrict__ Ag, const __half* __restrict__ Bg,
       const float* __restrict__ bias, void* __restrict__ Cg,
       int K, int lda, int ldb, int ldc,
       long long sA, long long sB, long long sC)
{
    extern __shared__ char sm[];
    const uint32_t smem0 = smem_u32(sm);

    const int tid  = threadIdx.x;
    const int lane = tid & 31;
    const int wid  = tid >> 5;
    const int wm   = (wid & 1) * 64;
    const int wn   = (wid >> 1) * 64;
    const int g    = lane >> 2;
    const int tc   = lane & 3;

    const __half* A = Ag + (long long)blockIdx.z * sA + (long long)(blockIdx.y * 128) * lda;
    const __half* B = Bg + (long long)blockIdx.z * sB + (long long)(blockIdx.x * 128) * ldb;

    // ldmatrix per-lane address components
    const int arow = (lane & 15);                 // row within 16-row group
    const int akx  = (lane >> 4) << 4;            // +16B for k8..k15 matrices
    const int brow = (lane & 7) + ((lane >> 4) & 1) * 8;
    const int bkx  = ((lane >> 3) & 1) << 4;

    float acc[4][8][4];
    #pragma unroll
    for (int i = 0; i < 4; i++)
        #pragma unroll
        for (int j = 0; j < 8; j++)
            #pragma unroll
            for (int k = 0; k < 4; k++) acc[i][j][k] = 0.f;

    const int nk = K >> 6;                        // K-chunks of 64
    cp_tile_h(smem0,         A, lda, tid);
    cp_tile_h(smem0 + 16384, B, ldb, tid);
    CP_COMMIT();

    for (int i = 0; i < nk; i++) {
        const int s = i & 1;
        if (i + 1 < nk) {
            const uint32_t nb = smem0 + (s ^ 1) * STAGE_BYTES;
            cp_tile_h(nb,         A + (i + 1) * 64, lda, tid);
            cp_tile_h(nb + 16384, B + (i + 1) * 64, ldb, tid);
            CP_COMMIT();
            CP_WAIT(1);
        } else {
            CP_WAIT(0);
        }
        __syncthreads();

        const uint32_t As = smem0 + s * STAGE_BYTES;
        const uint32_t Bs = As + 16384;
        #pragma unroll
        for (int ks = 0; ks < 4; ks++) {
            const int kb = ks * 32;               // byte offset of k-step
            unsigned a[4][4], b[4][4];
            #pragma unroll
            for (int mf = 0; mf < 4; mf++) {
                int r = wm + mf * 16 + arow;
                ldm_x4(a[mf], As + r * 128 + (((kb + akx)) ^ ((r & 7) << 4)));
            }
            #pragma unroll
            for (int p = 0; p < 4; p++) {
                int r = wn + p * 16 + brow;
                ldm_x4(b[p], Bs + r * 128 + (((kb + bkx)) ^ ((r & 7) << 4)));
            }
            #pragma unroll
            for (int mf = 0; mf < 4; mf++)
                #pragma unroll
                for (int p = 0; p < 4; p++) {
                    mma_f16(acc[mf][2 * p],     a[mf], &b[p][0]);
                    mma_f16(acc[mf][2 * p + 1], a[mf], &b[p][2]);
                }
        }
        __syncthreads();
    }

    // ------------------------- epilogue -------------------------------------
    #pragma unroll
    for (int mf = 0; mf < 4; mf++) {
        #pragma unroll
        for (int nf = 0; nf < 8; nf++) {
            const int r0 = blockIdx.y * 128 + wm + mf * 16 + g;
            const int c  = blockIdx.x * 128 + wn + nf * 8 + 2 * tc;
            float v0 = acc[mf][nf][0], v1 = acc[mf][nf][1];
            float v2 = acc[mf][nf][2], v3 = acc[mf][nf][3];
            if (BIAS == 1) {
                const float b0 = bias[c], b1 = bias[c + 1];
                v0 += b0; v1 += b1; v2 += b0; v3 += b1;
            } else if (BIAS == 2) {
                const float br0 = bias[r0], br1 = bias[r0 + 8];
                v0 += br0; v1 += br0; v2 += br1; v3 += br1;
            }
            if (OUTF) {
                float* Cb = (float*)Cg + (long long)blockIdx.z * sC;
                *reinterpret_cast<float2*>(Cb + (long long)r0 * ldc + c)       = make_float2(v0, v1);
                *reinterpret_cast<float2*>(Cb + (long long)(r0 + 8) * ldc + c) = make_float2(v2, v3);
            } else {
                __half* Cb = (__half*)Cg + (long long)blockIdx.z * sC;
                *reinterpret_cast<__half2*>(Cb + (long long)r0 * ldc + c)       = __floats2half2_rn(v0, v1);
                *reinterpret_cast<__half2*>(Cb + (long long)(r0 + 8) * ldc + c) = __floats2half2_rn(v2, v3);
            }
        }
    }
}

// ------------------------- masked softmax over k -----------------------------
// reads f32 logits, writes f16 attention weights
__global__ void softmax_kernel(const float* __restrict__ attn,
                               __half* __restrict__ attn_h,
                               const void* __restrict__ mask_raw)
{
    const long long row = blockIdx.x;
    const float* p = attn + row * CDIM;
    __half* po = attn_h + row * CDIM;
    const float scale = rsqrtf((float)CDIM);
    const int tid = threadIdx.x;
    const int mode = g_mask_mode;

    const unsigned char* mb = (const unsigned char*)mask_raw + row * CDIM;
    const int*           mi = (const int*)mask_raw          + row * CDIM;
    const float*         mf = (const float*)mask_raw        + row * CDIM;

    float v[8];
    bool mm[8];
    float lmax = -INFINITY;
    #pragma unroll
    for (int i = 0; i < 8; i++) {
        int e = tid + i * 256;
        bool masked;
        if      (mode == 0) masked = (mb[e] != 0);
        else if (mode == 1) masked = (mi[e] != 0);
        else                masked = (mf[e] != 0.f);
        mm[i] = masked;
        float t = masked ? -INFINITY : p[e] * scale;
        v[i] = t;
        lmax = fmaxf(lmax, t);
    }

    __shared__ float red[256];
    red[tid] = lmax; __syncthreads();
    #pragma unroll
    for (int s = 128; s > 0; s >>= 1) {
        if (tid < s) red[tid] = fmaxf(red[tid], red[tid + s]);
        __syncthreads();
    }
    const float rmax = red[0];
    __syncthreads();

    float lsum = 0.f;
    #pragma unroll
    for (int i = 0; i < 8; i++) {
        v[i] = mm[i] ? 0.f : __expf(v[i] - rmax);
        lsum += v[i];
    }
    red[tid] = lsum; __syncthreads();
    #pragma unroll
    for (int s = 128; s > 0; s >>= 1) {
        if (tid < s) red[tid] += red[tid + s];
        __syncthreads();
    }
    const float inv = 1.f / red[0];
    #pragma unroll
    for (int i = 0; i < 8; i++)
        po[tid + i * 256] = __float2half_rn(v[i] * inv);
}

// ---------------------------------------------------------------------------
extern "C" void kernel_launch(void* const* d_in, const int* in_sizes, int n_in,
                              void* d_out, int out_size)
{
    const float* x     = (const float*)d_in[0];   // [B,C,E]
    const float* fc_w  = (const float*)d_in[1];   // [E,E]
    const float* fc_b  = (const float*)d_in[2];   // [E]
    const float* alt_w = (const float*)d_in[3];   // [C,C]
    const float* alt_b = (const float*)d_in[4];   // [C]
    const float* v_w   = (const float*)d_in[5];   // [E,E]
    const float* v_b   = (const float*)d_in[6];   // [E]
    const void*  mask  = d_in[7];                 // [B,C,C] bool (encoding detected)
    float* out = (float*)d_out;                   // [B,C,E]

    __half *xh, *xTh, *yh, *zh, *vxTh, *fwh, *vwh, *awh, *attnh;
    float  *attn;
    cudaGetSymbolAddress((void**)&xh,    g_xh);
    cudaGetSymbolAddress((void**)&xTh,   g_xTh);
    cudaGetSymbolAddress((void**)&yh,    g_yh);
    cudaGetSymbolAddress((void**)&zh,    g_zh);
    cudaGetSymbolAddress((void**)&vxTh,  g_vxTh);
    cudaGetSymbolAddress((void**)&fwh,   g_fwh);
    cudaGetSymbolAddress((void**)&vwh,   g_vwh);
    cudaGetSymbolAddress((void**)&awh,   g_awh);
    cudaGetSymbolAddress((void**)&attn,  g_attn);
    cudaGetSymbolAddress((void**)&attnh, g_attnh);

    cudaFuncSetAttribute(gemm_h<0,0>, cudaFuncAttributeMaxDynamicSharedMemorySize, SMEM_DYN);
    cudaFuncSetAttribute(gemm_h<0,1>, cudaFuncAttributeMaxDynamicSharedMemorySize, SMEM_DYN);
    cudaFuncSetAttribute(gemm_h<1,0>, cudaFuncAttributeMaxDynamicSharedMemorySize, SMEM_DYN);
    cudaFuncSetAttribute(gemm_h<2,0>, cudaFuncAttributeMaxDynamicSharedMemorySize, SMEM_DYN);

    const long long sCE = (long long)CDIM * EDIM;
    const long long sCC = (long long)CDIM * CDIM;
    dim3 blk(128);

    // 0) mask encoding + fp16 conversion of all GEMM inputs
    detect_mask_kernel<<<1, 256>>>((const unsigned int*)mask, 16384);
    {
        int n4;
        n4 = (BATCH * CDIM * EDIM) / 4;
        cvt_kernel<<<(n4 + 255) / 256, 256>>>((const float4*)x, (__half2*)xh, n4);
        n4 = (EDIM * EDIM) / 4;
        cvt_kernel<<<(n4 + 255) / 256, 256>>>((const float4*)fc_w, (__half2*)fwh, n4);
        cvt_kernel<<<(n4 + 255) / 256, 256>>>((const float4*)v_w,  (__half2*)vwh, n4);
        n4 = (CDIM * CDIM) / 4;
        cvt_kernel<<<(n4 + 255) / 256, 256>>>((const float4*)alt_w, (__half2*)awh, n4);
    }
    transpose_kernel<<<dim3(EDIM / 32, CDIM / 32, BATCH), dim3(32, 8)>>>(x, xTh);

    // 1) y[c,f]   = sum_e x[c,e]*fc_w[f,e] + fc_b[f]      M=C,N=E,K=E (col bias)
    gemm_h<1,0><<<dim3(EDIM / 128, CDIM / 128, BATCH), blk, SMEM_DYN>>>(
        xh, fwh, fc_b, yh, EDIM, EDIM, EDIM, EDIM, sCE, 0, sCE);

    // 2) vxT[f,k] = sum_e v_w[f,e]*x[k,e] + v_b[f]        M=E,N=C,K=E (row bias)
    gemm_h<2,0><<<dim3(CDIM / 128, EDIM / 128, BATCH), blk, SMEM_DYN>>>(
        vwh, xh, v_b, vxTh, EDIM, EDIM, EDIM, CDIM, 0, sCE, sCE);

    // 3) z[k,e]   = sum_c alt_w[k,c]*xT[e,c] + alt_b[k]   M=C,N=E,K=C (row bias)
    gemm_h<2,0><<<dim3(EDIM / 128, CDIM / 128, BATCH), blk, SMEM_DYN>>>(
        awh, xTh, alt_b, zh, CDIM, CDIM, CDIM, EDIM, 0, sCE, sCE);

    // 4) attn[c,k] = sum_e y[c,e]*z[k,e]                  M=C,N=C,K=E (f32 out)
    gemm_h<0,1><<<dim3(CDIM / 128, CDIM / 128, BATCH), blk, SMEM_DYN>>>(
        yh, zh, nullptr, attn, EDIM, EDIM, EDIM, CDIM, sCE, sCE, sCC);

    // 5) masked softmax over k -> fp16 weights
    softmax_kernel<<<BATCH * CDIM, 256>>>(attn, attnh, mask);

    // 6) out[c,e] = sum_k attn[c,k]*vxT[e,k]              M=C,N=E,K=C (f32 out)
    gemm_h<0,1><<<dim3(EDIM / 128, CDIM / 128, BATCH), blk, SMEM_DYN>>>(
        attnh, vxTh, nullptr, out, CDIM, CDIM, CDIM, EDIM, sCC, sCE, sCE);
}

// round 6
// speedup vs baseline: 7.8465x; 1.0339x over previous
#include <cuda_runtime.h>
#include <cuda_fp16.h>
#include <cstdint>
#include <math.h>

#define BATCH 4
#define CDIM  2048
#define EDIM  1024

// ------------------------- scratch (__device__ globals) ---------------------
__device__ __half g_xh  [(size_t)BATCH * CDIM * EDIM];  // x    [b,C,E] fp16
__device__ __half g_xTh [(size_t)BATCH * CDIM * EDIM];  // xT   [b,E,C] fp16
__device__ __half g_yh  [(size_t)BATCH * CDIM * EDIM];  // y    [b,C,E] fp16
__device__ __half g_zh  [(size_t)BATCH * CDIM * EDIM];  // z    [b,C,E] fp16
__device__ __half g_vxTh[(size_t)BATCH * CDIM * EDIM];  // vxT  [b,E,C] fp16
__device__ __half g_fwh [(size_t)EDIM * EDIM];          // fp16 weights
__device__ __half g_vwh [(size_t)EDIM * EDIM];
__device__ __half g_awh [(size_t)CDIM * CDIM];
__device__ __half g_lgh  [(size_t)BATCH * CDIM * CDIM]; // attn logits*scale f16
__device__ __half g_attnh[(size_t)BATCH * CDIM * CDIM]; // attn weights fp16
__device__ int    g_mask_mode;                          // 0=u8, 1=i32, 2=f32

// ------------------------- helpers ------------------------------------------
__device__ __forceinline__ uint32_t smem_u32(const void* p) {
    uint32_t a;
    asm("{ .reg .u64 t; cvta.to.shared.u64 t, %1; cvt.u32.u64 %0, t; }"
        : "=r"(a) : "l"(p));
    return a;
}
__device__ __forceinline__ void ldm_x4(unsigned* r, uint32_t addr) {
    asm volatile("ldmatrix.sync.aligned.m8n8.x4.shared.b16 {%0,%1,%2,%3}, [%4];"
                 : "=r"(r[0]), "=r"(r[1]), "=r"(r[2]), "=r"(r[3]) : "r"(addr));
}
__device__ __forceinline__ void mma_f16(float* c, const unsigned* a, const unsigned* b) {
    asm volatile(
        "mma.sync.aligned.m16n8k16.row.col.f32.f16.f16.f32 "
        "{%0,%1,%2,%3}, {%4,%5,%6,%7}, {%8,%9}, {%0,%1,%2,%3};"
        : "+f"(c[0]), "+f"(c[1]), "+f"(c[2]), "+f"(c[3])
        : "r"(a[0]), "r"(a[1]), "r"(a[2]), "r"(a[3]), "r"(b[0]), "r"(b[1]));
}
#define CP_COMMIT() asm volatile("cp.async.commit_group;" ::: "memory")
#define CP_WAIT(n)  asm volatile("cp.async.wait_group %0;" :: "n"(n) : "memory")

// ------------------------- mask-mode detection ------------------------------
__global__ void detect_mask_kernel(const unsigned int* __restrict__ w, int nwords)
{
    __shared__ int sawFloat, sawMulti;
    if (threadIdx.x == 0) { sawFloat = 0; sawMulti = 0; }
    __syncthreads();
    for (int i = threadIdx.x; i < nwords; i += blockDim.x) {
        unsigned int v = w[i];
        if (v == 0x3F800000u) atomicOr(&sawFloat, 1);
        else if (v > 1u)      atomicOr(&sawMulti, 1);
    }
    __syncthreads();
    if (threadIdx.x == 0)
        g_mask_mode = sawFloat ? 2 : (sawMulti ? 0 : 1);
}

// ------------------------- f32 -> f16 conversion ----------------------------
__global__ void cvt_kernel(const float4* __restrict__ in, __half2* __restrict__ out, int n4)
{
    int i = blockIdx.x * 256 + threadIdx.x;
    if (i < n4) {
        float4 v = in[i];
        out[2 * i]     = __floats2half2_rn(v.x, v.y);
        out[2 * i + 1] = __floats2half2_rn(v.z, v.w);
    }
}

// --------------- transpose+cvt: x f32 -> xh [C,E] f16 AND xTh [E,C] f16 -----
__global__ void transpose_dual_kernel(const float* __restrict__ in,
                                      __half* __restrict__ xh,
                                      __half* __restrict__ xTh)
{
    __shared__ float t[32][33];
    const long long boff = (long long)blockIdx.z * CDIM * EDIM;
    const int e0 = blockIdx.x * 32, c0 = blockIdx.y * 32;
    const int tx = threadIdx.x, ty = threadIdx.y;   // (32, 8)
    #pragma unroll
    for (int j = 0; j < 32; j += 8) {
        float v = in[boff + (long long)(c0 + ty + j) * EDIM + e0 + tx];
        t[ty + j][tx] = v;
        xh[boff + (long long)(c0 + ty + j) * EDIM + e0 + tx] = __float2half_rn(v);
    }
    __syncthreads();
    #pragma unroll
    for (int j = 0; j < 32; j += 8)
        xTh[boff + (long long)(e0 + ty + j) * CDIM + c0 + tx] = __float2half_rn(t[tx][ty + j]);
}

// ---------------------------------------------------------------------------
// FP16 mma.sync NT GEMM (multi-op): C[m,n] = sum_k A[m,k]*B[n,k] (+f32 bias)
// Block 128x128, K-chunk 64 halves (128B rows, XOR swizzle), 4 warps (2x2,
// warp tile 64x64), cp.async 3-stage pipeline (single barrier per K-iter),
// ldmatrix.x4 fragments. Op selected by blockIdx.z>>2, batch = blockIdx.z&3.
// biasMode: 0=none, 1=col, 2=row. outMode: 0=f16, 1=f32, 2=f16*SCALE.
// ---------------------------------------------------------------------------
#define STAGE_BYTES 32768                 // A 16KB + B 16KB
#define SMEM_DYN   (3 * STAGE_BYTES)      // 96 KB

#define ATT_SCALE 0.022097086912079612f   // 1/sqrt(2048)

struct GOp {
    const __half* A; const __half* B; const float* bias; void* C;
    long long sA, sB, sC;
    int K, lda, ldb, ldc, biasMode, outMode, nbx;
};
struct GParams { GOp op[3]; };

__device__ __forceinline__ void cp_tile_h(uint32_t base, const __half* g, int ld, int tid)
{
    #pragma unroll
    for (int l = 0; l < 8; l++) {
        int idx = tid + l * 128;          // 0..1023
        int r  = idx >> 3;                // 0..127
        int cb = (idx & 7) << 4;          // byte col 0..112
        uint32_t dst = base + r * 128 + (cb ^ ((r & 7) << 4));
        const __half* src = g + (long long)r * ld + (cb >> 1);
        asm volatile("cp.async.cg.shared.global [%0], [%1], 16;"
                     :: "r"(dst), "l"(src) : "memory");
    }
}

__global__ void __launch_bounds__(128, 2)
gemm_any(GParams P)
{
    extern __shared__ char sm[];
    const uint32_t smem0 = smem_u32(sm);

    const GOp o = P.op[blockIdx.z >> 2];
    const int batch = blockIdx.z & 3;
    const int bx = blockIdx.x % o.nbx;
    const int by = blockIdx.x / o.nbx;

    const int tid  = threadIdx.x;
    const int lane = tid & 31;
    const int wid  = tid >> 5;
    const int wm   = (wid & 1) * 64;
    const int wn   = (wid >> 1) * 64;
    const int g    = lane >> 2;
    const int tc   = lane & 3;

    const __half* A = o.A + (long long)batch * o.sA + (long long)(by * 128) * o.lda;
    const __half* B = o.B + (long long)batch * o.sB + (long long)(bx * 128) * o.ldb;

    // ldmatrix per-lane address components
    const int arow = (lane & 15);
    const int akx  = (lane >> 4) << 4;
    const int brow = (lane & 7) + ((lane >> 4) & 1) * 8;
    const int bkx  = ((lane >> 3) & 1) << 4;

    float acc[4][8][4];
    #pragma unroll
    for (int i = 0; i < 4; i++)
        #pragma unroll
        for (int j = 0; j < 8; j++)
            #pragma unroll
            for (int k = 0; k < 4; k++) acc[i][j][k] = 0.f;

    const int nk = o.K >> 6;              // K-chunks of 64 (always >= 16)

    cp_tile_h(smem0,         A, o.lda, tid);
    cp_tile_h(smem0 + 16384, B, o.ldb, tid);
    CP_COMMIT();
    cp_tile_h(smem0 + STAGE_BYTES,         A + 64, o.lda, tid);
    cp_tile_h(smem0 + STAGE_BYTES + 16384, B + 64, o.ldb, tid);
    CP_COMMIT();

    int s = 0;
    for (int i = 0; i < nk; i++) {
        if (i + 1 < nk) CP_WAIT(1); else CP_WAIT(0);
        __syncthreads();
        if (i + 2 < nk) {
            int s2 = s + 2; if (s2 >= 3) s2 -= 3;
            const uint32_t nb = smem0 + s2 * STAGE_BYTES;
            cp_tile_h(nb,         A + (i + 2) * 64, o.lda, tid);
            cp_tile_h(nb + 16384, B + (i + 2) * 64, o.ldb, tid);
            CP_COMMIT();
        }

        const uint32_t As = smem0 + s * STAGE_BYTES;
        const uint32_t Bs = As + 16384;
        #pragma unroll
        for (int ks = 0; ks < 4; ks++) {
            const int kb = ks * 32;
            unsigned a[4][4], b[4][4];
            #pragma unroll
            for (int mf = 0; mf < 4; mf++) {
                int r = wm + mf * 16 + arow;
                ldm_x4(a[mf], As + r * 128 + ((kb + akx) ^ ((r & 7) << 4)));
            }
            #pragma unroll
            for (int p = 0; p < 4; p++) {
                int r = wn + p * 16 + brow;
                ldm_x4(b[p], Bs + r * 128 + ((kb + bkx) ^ ((r & 7) << 4)));
            }
            #pragma unroll
            for (int mf = 0; mf < 4; mf++)
                #pragma unroll
                for (int p = 0; p < 4; p++) {
                    mma_f16(acc[mf][2 * p],     a[mf], &b[p][0]);
                    mma_f16(acc[mf][2 * p + 1], a[mf], &b[p][2]);
                }
        }
        if (++s == 3) s = 0;
    }

    // ------------------------- epilogue -------------------------------------
    #pragma unroll
    for (int mf = 0; mf < 4; mf++) {
        #pragma unroll
        for (int nf = 0; nf < 8; nf++) {
            const int r0 = by * 128 + wm + mf * 16 + g;
            const int c  = bx * 128 + wn + nf * 8 + 2 * tc;
            float v0 = acc[mf][nf][0], v1 = acc[mf][nf][1];
            float v2 = acc[mf][nf][2], v3 = acc[mf][nf][3];
            if (o.biasMode == 1) {
                const float b0 = o.bias[c], b1 = o.bias[c + 1];
                v0 += b0; v1 += b1; v2 += b0; v3 += b1;
            } else if (o.biasMode == 2) {
                const float br0 = o.bias[r0], br1 = o.bias[r0 + 8];
                v0 += br0; v1 += br0; v2 += br1; v3 += br1;
            }
            if (o.outMode == 1) {
                float* Cb = (float*)o.C + (long long)batch * o.sC;
                *reinterpret_cast<float2*>(Cb + (long long)r0 * o.ldc + c)       = make_float2(v0, v1);
                *reinterpret_cast<float2*>(Cb + (long long)(r0 + 8) * o.ldc + c) = make_float2(v2, v3);
            } else {
                const float scl = (o.outMode == 2) ? ATT_SCALE : 1.f;
                __half* Cb = (__half*)o.C + (long long)batch * o.sC;
                *reinterpret_cast<__half2*>(Cb + (long long)r0 * o.ldc + c)       = __floats2half2_rn(v0 * scl, v1 * scl);
                *reinterpret_cast<__half2*>(Cb + (long long)(r0 + 8) * o.ldc + c) = __floats2half2_rn(v2 * scl, v3 * scl);
            }
        }
    }
}

// ------------------------- masked softmax over k -----------------------------
// reads f16 pre-scaled logits, writes f16 attention weights
__global__ void softmax_kernel(const __half* __restrict__ lg,
                               __half* __restrict__ attn_h,
                               const void* __restrict__ mask_raw)
{
    const long long row = blockIdx.x;
    const __half* p = lg + row * CDIM;
    __half* po = attn_h + row * CDIM;
    const int tid = threadIdx.x;
    const int mode = g_mask_mode;

    const unsigned char* mb = (const unsigned char*)mask_raw + row * CDIM;
    const int*           mi = (const int*)mask_raw          + row * CDIM;
    const float*         mf = (const float*)mask_raw        + row * CDIM;

    float v[8];
    bool mm[8];
    float lmax = -INFINITY;
    #pragma unroll
    for (int i = 0; i < 8; i++) {
        int e = tid + i * 256;
        bool masked;
        if      (mode == 0) masked = (mb[e] != 0);
        else if (mode == 1) masked = (mi[e] != 0);
        else                masked = (mf[e] != 0.f);
        mm[i] = masked;
        float t = masked ? -INFINITY : __half2float(p[e]);
        v[i] = t;
        lmax = fmaxf(lmax, t);
    }

    __shared__ float red[256];
    red[tid] = lmax; __syncthreads();
    #pragma unroll
    for (int s = 128; s > 0; s >>= 1) {
        if (tid < s) red[tid] = fmaxf(red[tid], red[tid + s]);
        __syncthreads();
    }
    const float rmax = red[0];
    __syncthreads();

    float lsum = 0.f;
    #pragma unroll
    for (int i = 0; i < 8; i++) {
        v[i] = mm[i] ? 0.f : __expf(v[i] - rmax);
        lsum += v[i];
    }
    red[tid] = lsum; __syncthreads();
    #pragma unroll
    for (int s = 128; s > 0; s >>= 1) {
        if (tid < s) red[tid] += red[tid + s];
        __syncthreads();
    }
    const float inv = 1.f / red[0];
    #pragma unroll
    for (int i = 0; i < 8; i++)
        po[tid + i * 256] = __float2half_rn(v[i] * inv);
}

// ---------------------------------------------------------------------------
extern "C" void kernel_launch(void* const* d_in, const int* in_sizes, int n_in,
                              void* d_out, int out_size)
{
    const float* x     = (const float*)d_in[0];   // [B,C,E]
    const float* fc_w  = (const float*)d_in[1];   // [E,E]
    const float* fc_b  = (const float*)d_in[2];   // [E]
    const float* alt_w = (const float*)d_in[3];   // [C,C]
    const float* alt_b = (const float*)d_in[4];   // [C]
    const float* v_w   = (const float*)d_in[5];   // [E,E]
    const float* v_b   = (const float*)d_in[6];   // [E]
    const void*  mask  = d_in[7];                 // [B,C,C] bool (encoding detected)
    float* out = (float*)d_out;                   // [B,C,E]

    __half *xh, *xTh, *yh, *zh, *vxTh, *fwh, *vwh, *awh, *lgh, *attnh;
    cudaGetSymbolAddress((void**)&xh,    g_xh);
    cudaGetSymbolAddress((void**)&xTh,   g_xTh);
    cudaGetSymbolAddress((void**)&yh,    g_yh);
    cudaGetSymbolAddress((void**)&zh,    g_zh);
    cudaGetSymbolAddress((void**)&vxTh,  g_vxTh);
    cudaGetSymbolAddress((void**)&fwh,   g_fwh);
    cudaGetSymbolAddress((void**)&vwh,   g_vwh);
    cudaGetSymbolAddress((void**)&awh,   g_awh);
    cudaGetSymbolAddress((void**)&lgh,   g_lgh);
    cudaGetSymbolAddress((void**)&attnh, g_attnh);

    cudaFuncSetAttribute(gemm_any, cudaFuncAttributeMaxDynamicSharedMemorySize, SMEM_DYN);

    const long long sCE = (long long)CDIM * EDIM;
    const long long sCC = (long long)CDIM * CDIM;

    // 0) mask encoding + fp16 conversions
    detect_mask_kernel<<<1, 256>>>((const unsigned int*)mask, 16384);
    {
        int n4 = (EDIM * EDIM) / 4;
        cvt_kernel<<<(n4 + 255) / 256, 256>>>((const float4*)fc_w, (__half2*)fwh, n4);
        cvt_kernel<<<(n4 + 255) / 256, 256>>>((const float4*)v_w,  (__half2*)vwh, n4);
        n4 = (CDIM * CDIM) / 4;
        cvt_kernel<<<(n4 + 255) / 256, 256>>>((const float4*)alt_w, (__half2*)awh, n4);
    }
    transpose_dual_kernel<<<dim3(EDIM / 32, CDIM / 32, BATCH), dim3(32, 8)>>>(x, xh, xTh);

    // 1-3) merged independent GEMMs (one launch, 1536 CTAs)
    //   g1: y[c,f]   = x[c,e]*fc_w[f,e] + fc_b[f]   M=C,N=E,K=E (col bias)
    //   g2: vxT[f,k] = v_w[f,e]*x[k,e] + v_b[f]     M=E,N=C,K=E (row bias)
    //   g3: z[k,e]   = alt_w[k,c]*xT[e,c] + alt_b[k] M=C,N=E,K=C (row bias)
    {
        GParams P;
        P.op[0] = { xh,  fwh, fc_b,  yh,   sCE, 0,   sCE, EDIM, EDIM, EDIM, EDIM, 1, 0, EDIM / 128 };
        P.op[1] = { vwh, xh,  v_b,   vxTh, 0,   sCE, sCE, EDIM, EDIM, EDIM, CDIM, 2, 0, CDIM / 128 };
        P.op[2] = { awh, xTh, alt_b, zh,   0,   sCE, sCE, CDIM, CDIM, CDIM, EDIM, 2, 0, EDIM / 128 };
        gemm_any<<<dim3(128, 1, 12), 128, SMEM_DYN>>>(P);
    }

    // 4) logits[c,k] = (sum_e y[c,e]*z[k,e]) * 1/sqrt(C)  -> f16
    {
        GParams P;
        P.op[0] = { yh, zh, nullptr, lgh, sCE, sCE, sCC, EDIM, EDIM, EDIM, CDIM, 0, 2, CDIM / 128 };
        gemm_any<<<dim3(256, 1, 4), 128, SMEM_DYN>>>(P);
    }

    // 5) masked softmax over k -> fp16 weights
    softmax_kernel<<<BATCH * CDIM, 256>>>(lgh, attnh, mask);

    // 6) out[c,e] = sum_k attn[c,k]*vxT[e,k]  (f32 out)
    {
        GParams P;
        P.op[0] = { attnh, vxTh, nullptr, out, sCC, sCE, sCE, CDIM, CDIM, CDIM, EDIM, 0, 1, EDIM / 128 };
        gemm_any<<<dim3(128, 1, 4), 128, SMEM_DYN>>>(P);
    }
}